// round 3
// baseline (speedup 1.0000x reference)
#include <cuda_runtime.h>
#include <math.h>
#include <stdint.h>

#define M_TOK 12608
#define C_DIM 768
#define H_DIM 3072

// ---------------- scratch (device globals; no allocation allowed) ----------------
__device__ int8_t  g_qa[(size_t)M_TOK * C_DIM];
__device__ int8_t  g_qw1[(size_t)H_DIM * C_DIM];
__device__ int8_t  g_qw2[(size_t)C_DIM * H_DIM];
__device__ int8_t  g_qh[(size_t)M_TOK * H_DIM];
__device__ float   g_h[(size_t)M_TOK * H_DIM];
__device__ float   g_xminC[C_DIM];
__device__ float   g_xmaxC[C_DIM];
__device__ float   g_w1cmax[C_DIM];
__device__ float   g_cs[C_DIM];
__device__ float   g_sw1[H_DIM];
__device__ float   g_sw2[C_DIM];
__device__ float   g_sx;
__device__ float   g_zp;
__device__ int     g_k128;   // 128 - zp
__device__ float   g_habs;
__device__ float   g_omin, g_omax;

// ---------------- atomic float min/max (ordered-int trick) ----------------
__device__ __forceinline__ void atomicMaxF(float* a, float v) {
    if (v >= 0.f) atomicMax((int*)a, __float_as_int(v));
    else          atomicMin((unsigned int*)a, __float_as_uint(v));
}
__device__ __forceinline__ void atomicMinF(float* a, float v) {
    if (v >= 0.f) atomicMin((int*)a, __float_as_int(v));
    else          atomicMax((unsigned int*)a, __float_as_uint(v));
}

// ---------------- XLA f32 erf (ErfImpl32): erf(x) = w*alpha(w^2)/beta(w^2), w=clamp(x,±4)
__device__ __forceinline__ float xla_erf(float x) {
    float w = fminf(fmaxf(x, -4.0f), 4.0f);
    float s = __fmul_rn(w, w);
    float num = -2.72614225801306e-10f;
    num = __fadd_rn(__fmul_rn(num, s),  2.77068142495902e-08f);
    num = __fadd_rn(__fmul_rn(num, s), -2.10102402082508e-06f);
    num = __fadd_rn(__fmul_rn(num, s), -5.69250639462346e-05f);
    num = __fadd_rn(__fmul_rn(num, s), -7.34990630326855e-04f);
    num = __fadd_rn(__fmul_rn(num, s), -2.95459980854025e-03f);
    num = __fadd_rn(__fmul_rn(num, s), -1.60960333262415e-02f);
    float den = -1.45660718464996e-05f;
    den = __fadd_rn(__fmul_rn(den, s), -2.13374055278905e-04f);
    den = __fadd_rn(__fmul_rn(den, s), -1.68282697438203e-03f);
    den = __fadd_rn(__fmul_rn(den, s), -7.37332916720468e-03f);
    den = __fadd_rn(__fmul_rn(den, s), -1.42647390514189e-02f);
    return __fdiv_rn(__fmul_rn(w, num), den);
}

__device__ __forceinline__ float xla_gelu(float x) {
    float u = __fdiv_rn(x, 1.4142135623730951f);
    float e = xla_erf(u);
    return __fmul_rn(__fmul_rn(x, __fadd_rn(e, 1.0f)), 0.5f);
}

// ---------------- init ----------------
__global__ void k_init() {
    int t = blockIdx.x * blockDim.x + threadIdx.x;
    if (t < C_DIM) {
        g_xminC[t]  = INFINITY;
        g_xmaxC[t]  = -INFINITY;
        g_w1cmax[t] = 0.f;
    }
    if (t == 0) { g_habs = 0.f; g_omin = INFINITY; g_omax = -INFINITY; }
}

// ---------------- per-channel min/max of x ----------------
__global__ void k_xstats(const float* __restrict__ x) {
    int c  = blockIdx.x * 256 + threadIdx.x;
    int m0 = blockIdx.y * 197;
    float mn = INFINITY, mx = -INFINITY;
    const float* p = x + (size_t)m0 * C_DIM + c;
    #pragma unroll 4
    for (int i = 0; i < 197; ++i) {
        float v = p[(size_t)i * C_DIM];
        mn = fminf(mn, v); mx = fmaxf(mx, v);
    }
    atomicMinF(&g_xminC[c], mn);
    atomicMaxF(&g_xmaxC[c], mx);
}

// ---------------- per-channel absmax of w1 ----------------
__global__ void k_w1stats(const float* __restrict__ w1) {
    int c  = blockIdx.x * 256 + threadIdx.x;
    int h0 = blockIdx.y * 256;
    float mx = 0.f;
    const float* p = w1 + (size_t)h0 * C_DIM + c;
    #pragma unroll 4
    for (int i = 0; i < 256; ++i)
        mx = fmaxf(mx, fabsf(p[(size_t)i * C_DIM]));
    atomicMax((int*)&g_w1cmax[c], __float_as_int(mx));
}

// ---------------- cs + activation scale/zp ----------------
__global__ void k_scalars() {
    __shared__ float smn[256], smx[256];
    int tid = threadIdx.x;
    const float LN2F = 0.6931471805599453f;
    float mn = INFINITY, mx = -INFINITY;
    for (int c = tid; c < C_DIM; c += 256) {
        float xlo = g_xminC[c], xhi = g_xmaxC[c];
        float gmax = fmaxf(fabsf(xlo), fabsf(xhi));
        float mw = g_w1cmax[c];
        float csr = __fdiv_rn(sqrtf(gmax), sqrtf(mw));
        float y = floorf(__fdiv_rn(logf(csr), LN2F));
        float p = exp2f(y);
        float cs = (__fsub_rn(csr, p) > __fsub_rn(__fmul_rn(2.f, p), csr)) ? 2.f * p : p;
        g_cs[c] = cs;
        mn = fminf(mn, __fdiv_rn(xlo, cs));
        mx = fmaxf(mx, __fdiv_rn(xhi, cs));
    }
    smn[tid] = mn; smx[tid] = mx;
    __syncthreads();
    for (int s = 128; s > 0; s >>= 1) {
        if (tid < s) {
            smn[tid] = fminf(smn[tid], smn[tid + s]);
            smx[tid] = fmaxf(smx[tid], smx[tid + s]);
        }
        __syncthreads();
    }
    if (tid == 0) {
        float xmn = fminf(smn[0], 0.f);
        float xmx = fmaxf(smx[0], 0.f);
        float s = fmaxf(__fdiv_rn(__fsub_rn(xmx, xmn), 255.f), 1e-8f);
        float zp = rintf(__fdiv_rn(-xmn, s));
        g_sx = s; g_zp = zp; g_k128 = 128 - (int)zp;
    }
}

// ---------------- quantize x -> s8 (q - 128) ----------------
__global__ void k_quant_x(const float* __restrict__ x) {
    size_t i = (size_t)blockIdx.x * 256 + threadIdx.x;
    if (i >= (size_t)M_TOK * C_DIM) return;
    int c = (int)(i % C_DIM);
    float s = g_sx, zp = g_zp;
    float t = __fdiv_rn(x[i], g_cs[c]);
    float q = __fadd_rn(rintf(__fdiv_rn(t, s)), zp);
    q = fminf(fmaxf(q, 0.f), 255.f);
    g_qa[i] = (int8_t)((int)q - 128);
}

// ---------------- quantize w1 * cs (per output row) ----------------
__global__ void k_quant_w1(const float* __restrict__ w1) {
    __shared__ float red[256];
    int j = blockIdx.x, tid = threadIdx.x;
    const float* row = w1 + (size_t)j * C_DIM;
    float mx = 0.f;
    for (int c = tid; c < C_DIM; c += 256)
        mx = fmaxf(mx, fabsf(__fmul_rn(row[c], g_cs[c])));
    red[tid] = mx; __syncthreads();
    for (int s = 128; s > 0; s >>= 1) {
        if (tid < s) red[tid] = fmaxf(red[tid], red[tid + s]);
        __syncthreads();
    }
    float sc = fmaxf(__fdiv_rn(red[0], 127.f), 1e-8f);
    __syncthreads();
    for (int c = tid; c < C_DIM; c += 256) {
        float ws = __fmul_rn(row[c], g_cs[c]);
        float q = rintf(__fdiv_rn(ws, sc));
        q = fminf(fmaxf(q, -128.f), 127.f);
        g_qw1[(size_t)j * C_DIM + c] = (int8_t)(int)q;
    }
    if (tid == 0) g_sw1[j] = sc;
}

// ---------------- quantize w2 (per output row) ----------------
__global__ void k_quant_w2(const float* __restrict__ w2) {
    __shared__ float red[256];
    int j = blockIdx.x, tid = threadIdx.x;
    const float* row = w2 + (size_t)j * H_DIM;
    float mx = 0.f;
    for (int c = tid; c < H_DIM; c += 256)
        mx = fmaxf(mx, fabsf(row[c]));
    red[tid] = mx; __syncthreads();
    for (int s = 128; s > 0; s >>= 1) {
        if (tid < s) red[tid] = fmaxf(red[tid], red[tid + s]);
        __syncthreads();
    }
    float sc = fmaxf(__fdiv_rn(red[0], 127.f), 1e-8f);
    __syncthreads();
    for (int c = tid; c < H_DIM; c += 256) {
        float q = rintf(__fdiv_rn(row[c], sc));
        q = fminf(fmaxf(q, -128.f), 127.f);
        g_qw2[(size_t)j * H_DIM + c] = (int8_t)(int)q;
    }
    if (tid == 0) g_sw2[j] = sc;
}

// =====================================================================
// GEMM1: fp32 FMA chain, k ascending, ONE accumulator per output.
// Inputs are the reference's dequantized fp32 values:
//   A[m,c] = fl32((q-zp) * sx),  B[h,c] = fl32(qw1 * sw1[h])
// This replicates the reference fp32 einsum's per-output sequential-k
// FMA accumulation bit-for-bit (Eigen GEBP / cutlass SIMT both do this).
// 128x128 tile, BK=16, 256 threads, 8x8 per thread. Stride-17 smem pad.
// =====================================================================
__global__ __launch_bounds__(256, 2) void k_gemm1f(const float* __restrict__ b1) {
    __shared__ float As[128 * 17], Bs[128 * 17];
    __shared__ float red[256];
    float acc[8][8];
    #pragma unroll
    for (int i = 0; i < 8; ++i)
        #pragma unroll
        for (int j = 0; j < 8; ++j) acc[i][j] = 0.f;

    const int tid = threadIdx.x;
    const int ldRow = tid >> 1, ldSeg = tid & 1;  // 2 threads per row, 8 bytes each
    const int tx = tid & 15, ty = tid >> 4;
    const int aRow = blockIdx.y * 128 + ldRow;
    const int bRow = blockIdx.x * 128 + ldRow;
    const bool aValid = (aRow < M_TOK);
    const float sx = g_sx;
    const float k128f = (float)g_k128;           // (q-zp) = a + (128-zp)
    const float swB = g_sw1[bRow];

    const int8_t* aP = g_qa + (size_t)aRow * C_DIM + ldSeg * 8;
    const int8_t* bP = g_qw1 + (size_t)bRow * C_DIM + ldSeg * 8;

    for (int kt = 0; kt < C_DIM; kt += 16) {
        uint2 avi = make_uint2(0u, 0u);
        if (aValid) avi = *reinterpret_cast<const uint2*>(aP + kt);
        uint2 bvi = *reinterpret_cast<const uint2*>(bP + kt);
        __syncthreads();
        {
            float* as = &As[ldRow * 17 + ldSeg * 8];
            float* bs = &Bs[ldRow * 17 + ldSeg * 8];
            #pragma unroll
            for (int t = 0; t < 4; ++t) {
                int a0 = (int)(int8_t)(avi.x >> (8 * t));
                int a1 = (int)(int8_t)(avi.y >> (8 * t));
                // A dequant: fl32((a + k128) * sx). (a+k128) integer, exact in f32.
                as[t]     = __fmul_rn((float)a0 + k128f, sx);
                as[t + 4] = __fmul_rn((float)a1 + k128f, sx);
                int b0 = (int)(int8_t)(bvi.x >> (8 * t));
                int b1v = (int)(int8_t)(bvi.y >> (8 * t));
                bs[t]     = __fmul_rn((float)b0, swB);
                bs[t + 4] = __fmul_rn((float)b1v, swB);
            }
        }
        __syncthreads();
        #pragma unroll
        for (int kk = 0; kk < 16; ++kk) {
            float a[8], b[8];
            #pragma unroll
            for (int i = 0; i < 8; ++i) a[i] = As[(ty + 16 * i) * 17 + kk];
            #pragma unroll
            for (int j = 0; j < 8; ++j) b[j] = Bs[(tx + 16 * j) * 17 + kk];
            #pragma unroll
            for (int i = 0; i < 8; ++i)
                #pragma unroll
                for (int j = 0; j < 8; ++j)
                    acc[i][j] = __fmaf_rn(a[i], b[j], acc[i][j]);
        }
    }

    // epilogue: h = chain + b1 (f32 add), exact GELU, max|h|
    float lmax = 0.f;
    #pragma unroll
    for (int j = 0; j < 8; ++j) {
        int col = blockIdx.x * 128 + tx + 16 * j;
        float bb = b1[col];
        #pragma unroll
        for (int i = 0; i < 8; ++i) {
            int row = blockIdx.y * 128 + ty + 16 * i;
            if (row < M_TOK) {
                float hv = __fadd_rn(acc[i][j], bb);
                float g = xla_gelu(hv);
                g_h[(size_t)row * H_DIM + col] = g;
                lmax = fmaxf(lmax, fabsf(g));
            }
        }
    }
    red[tid] = lmax; __syncthreads();
    for (int s = 128; s > 0; s >>= 1) {
        if (tid < s) red[tid] = fmaxf(red[tid], red[tid + s]);
        __syncthreads();
    }
    if (tid == 0) atomicMax((int*)&g_habs, __float_as_int(red[0]));
}

// ---------------- symmetric quantize h -> s8 ----------------
__global__ void k_quant_h() {
    size_t i = (size_t)blockIdx.x * 256 + threadIdx.x;
    if (i >= (size_t)M_TOK * H_DIM) return;
    float sh = fmaxf(__fdiv_rn(g_habs, 127.f), 1e-8f);
    float q = rintf(__fdiv_rn(g_h[i], sh));
    q = fminf(fmaxf(q, -128.f), 127.f);
    g_qh[i] = (int8_t)(int)q;
}

// ---------------- GEMM2: dp4a integer (exact), fl32 once, + b2 in f32 ----------------
__global__ __launch_bounds__(256, 2) void k_gemm2(const float* __restrict__ b2,
                                                  float* __restrict__ out) {
    __shared__ uint32_t As[128 * 9], Bs[128 * 9];
    __shared__ float red[256];
    int acc[8][8];
    #pragma unroll
    for (int i = 0; i < 8; ++i)
        #pragma unroll
        for (int j = 0; j < 8; ++j) acc[i][j] = 0;

    const int tid = threadIdx.x;
    const int ldRow = tid >> 1, ldSeg = tid & 1;
    const int tx = tid & 15, ty = tid >> 4;
    const int aRow = blockIdx.y * 128 + ldRow;
    const int bRow = blockIdx.x * 128 + ldRow;
    const int8_t* aP = g_qh + (size_t)aRow * H_DIM + ldSeg * 16;
    const int8_t* bP = g_qw2 + (size_t)bRow * H_DIM + ldSeg * 16;
    const bool aValid = (aRow < M_TOK);

    for (int kt = 0; kt < H_DIM; kt += 32) {
        uint4 av = make_uint4(0u, 0u, 0u, 0u);
        if (aValid) av = *reinterpret_cast<const uint4*>(aP + kt);
        uint4 bv = *reinterpret_cast<const uint4*>(bP + kt);
        __syncthreads();
        uint32_t* as = &As[ldRow * 9 + ldSeg * 4];
        as[0] = av.x; as[1] = av.y; as[2] = av.z; as[3] = av.w;
        uint32_t* bs = &Bs[ldRow * 9 + ldSeg * 4];
        bs[0] = bv.x; bs[1] = bv.y; bs[2] = bv.z; bs[3] = bv.w;
        __syncthreads();
        #pragma unroll
        for (int kk = 0; kk < 8; ++kk) {
            uint32_t a[8], b[8];
            #pragma unroll
            for (int i = 0; i < 8; ++i) a[i] = As[(ty + 16 * i) * 9 + kk];
            #pragma unroll
            for (int jj = 0; jj < 8; ++jj) b[jj] = Bs[(tx + 16 * jj) * 9 + kk];
            #pragma unroll
            for (int i = 0; i < 8; ++i)
                #pragma unroll
                for (int jj = 0; jj < 8; ++jj)
                    acc[i][jj] = __dp4a((int)a[i], (int)b[jj], acc[i][jj]);
        }
    }

    const double sh = (double)fmaxf(__fdiv_rn(g_habs, 127.f), 1e-8f);
    float lmin = INFINITY, lmax = -INFINITY;
    #pragma unroll
    for (int j = 0; j < 8; ++j) {
        int col = blockIdx.x * 128 + tx + 16 * j;
        double coef = sh * (double)g_sw2[col];
        float bb = b2[col];
        #pragma unroll
        for (int i = 0; i < 8; ++i) {
            int row = blockIdx.y * 128 + ty + 16 * i;
            if (row < M_TOK) {
                float dot = (float)(coef * (double)acc[i][j]);  // fl32(exact dot)
                float v = __fadd_rn(dot, bb);                   // + b2 in f32
                out[(size_t)row * C_DIM + col] = v;
                lmin = fminf(lmin, v);
                lmax = fmaxf(lmax, v);
            }
        }
    }
    red[tid] = lmax; __syncthreads();
    for (int s = 128; s > 0; s >>= 1) {
        if (tid < s) red[tid] = fmaxf(red[tid], red[tid + s]);
        __syncthreads();
    }
    if (tid == 0) atomicMaxF(&g_omax, red[0]);
    __syncthreads();
    red[tid] = lmin; __syncthreads();
    for (int s = 128; s > 0; s >>= 1) {
        if (tid < s) red[tid] = fminf(red[tid], red[tid + s]);
        __syncthreads();
    }
    if (tid == 0) atomicMinF(&g_omin, red[0]);
}

// ---------------- final asymmetric fake-quant of out (in place) ----------------
__global__ void k_quant_out(float* __restrict__ out) {
    size_t i = (size_t)blockIdx.x * 256 + threadIdx.x;
    if (i >= (size_t)M_TOK * C_DIM) return;
    float omn = fminf(g_omin, 0.f);
    float omx = fmaxf(g_omax, 0.f);
    float s = fmaxf(__fdiv_rn(__fsub_rn(omx, omn), 255.f), 1e-8f);
    float zp = rintf(__fdiv_rn(-omn, s));
    float v = out[i];
    float q = fminf(fmaxf(__fadd_rn(rintf(__fdiv_rn(v, s)), zp), 0.f), 255.f);
    out[i] = __fmul_rn(__fsub_rn(q, zp), s);
}

// ---------------- launch ----------------
extern "C" void kernel_launch(void* const* d_in, const int* in_sizes, int n_in,
                              void* d_out, int out_size) {
    const float* x  = (const float*)d_in[0];
    const float* w1 = (const float*)d_in[1];
    const float* b1 = (const float*)d_in[2];
    const float* w2 = (const float*)d_in[3];
    const float* b2 = (const float*)d_in[4];
    float* out = (float*)d_out;

    k_init<<<3, 256>>>();
    k_xstats<<<dim3(3, 64), 256>>>(x);
    k_w1stats<<<dim3(3, 12), 256>>>(w1);
    k_scalars<<<1, 256>>>();

    size_t nx = (size_t)M_TOK * C_DIM;
    k_quant_x<<<(unsigned)((nx + 255) / 256), 256>>>(x);
    k_quant_w1<<<H_DIM, 256>>>(w1);
    k_quant_w2<<<C_DIM, 256>>>(w2);

    k_gemm1f<<<dim3(H_DIM / 128, (M_TOK + 127) / 128), 256>>>(b1);

    size_t nh = (size_t)M_TOK * H_DIM;
    k_quant_h<<<(unsigned)((nh + 255) / 256), 256>>>();

    k_gemm2<<<dim3(C_DIM / 128, (M_TOK + 127) / 128), 256>>>(b2, out);

    k_quant_out<<<(unsigned)((nx + 255) / 256), 256>>>(out);
}

// round 4
// speedup vs baseline: 1.0852x; 1.0852x over previous
#include <cuda_runtime.h>
#include <math.h>
#include <stdint.h>

#define M_TOK 12608
#define C_DIM 768
#define H_DIM 3072

// ---------------- scratch (device globals; no allocation allowed) ----------------
__device__ int8_t  g_qa[(size_t)M_TOK * C_DIM];
__device__ int8_t  g_qw1[(size_t)H_DIM * C_DIM];
__device__ int8_t  g_qw2[(size_t)C_DIM * H_DIM];
__device__ int8_t  g_qh[(size_t)M_TOK * H_DIM];
__device__ float   g_h[(size_t)M_TOK * H_DIM];
__device__ float   g_xminC[C_DIM];
__device__ float   g_xmaxC[C_DIM];
__device__ float   g_w1cmax[C_DIM];
__device__ float   g_cs[C_DIM];
__device__ float   g_sw1[H_DIM];
__device__ float   g_sw2[C_DIM];
__device__ float   g_sx;
__device__ float   g_zp;
__device__ int     g_k128;   // 128 - zp
__device__ float   g_habs;
__device__ float   g_omin, g_omax;

// ---------------- f32x2 packed helpers (sm_103a FFMA2 pipe) ----------------
__device__ __forceinline__ unsigned long long pk2(float lo, float hi) {
    unsigned long long r;
    asm("mov.b64 %0, {%1, %2};" : "=l"(r) : "f"(lo), "f"(hi));
    return r;
}
__device__ __forceinline__ void upk2(unsigned long long v, float& lo, float& hi) {
    asm("mov.b64 {%0, %1}, %2;" : "=f"(lo), "=f"(hi) : "l"(v));
}
__device__ __forceinline__ unsigned long long fma2(unsigned long long a,
                                                   unsigned long long b,
                                                   unsigned long long c) {
    unsigned long long d;
    asm("fma.rn.f32x2 %0, %1, %2, %3;" : "=l"(d) : "l"(a), "l"(b), "l"(c));
    return d;
}

// ---------------- atomic float min/max (ordered-int trick) ----------------
__device__ __forceinline__ void atomicMaxF(float* a, float v) {
    if (v >= 0.f) atomicMax((int*)a, __float_as_int(v));
    else          atomicMin((unsigned int*)a, __float_as_uint(v));
}
__device__ __forceinline__ void atomicMinF(float* a, float v) {
    if (v >= 0.f) atomicMin((int*)a, __float_as_int(v));
    else          atomicMax((unsigned int*)a, __float_as_uint(v));
}

// ---------------- XLA f32 erf (ErfImpl32): erf(x) = w*alpha(w^2)/beta(w^2), w=clamp(x,±4)
__device__ __forceinline__ float xla_erf(float x) {
    float w = fminf(fmaxf(x, -4.0f), 4.0f);
    float s = __fmul_rn(w, w);
    float num = -2.72614225801306e-10f;
    num = __fadd_rn(__fmul_rn(num, s),  2.77068142495902e-08f);
    num = __fadd_rn(__fmul_rn(num, s), -2.10102402082508e-06f);
    num = __fadd_rn(__fmul_rn(num, s), -5.69250639462346e-05f);
    num = __fadd_rn(__fmul_rn(num, s), -7.34990630326855e-04f);
    num = __fadd_rn(__fmul_rn(num, s), -2.95459980854025e-03f);
    num = __fadd_rn(__fmul_rn(num, s), -1.60960333262415e-02f);
    float den = -1.45660718464996e-05f;
    den = __fadd_rn(__fmul_rn(den, s), -2.13374055278905e-04f);
    den = __fadd_rn(__fmul_rn(den, s), -1.68282697438203e-03f);
    den = __fadd_rn(__fmul_rn(den, s), -7.37332916720468e-03f);
    den = __fadd_rn(__fmul_rn(den, s), -1.42647390514189e-02f);
    return __fdiv_rn(__fmul_rn(w, num), den);
}

__device__ __forceinline__ float xla_gelu(float x) {
    float u = __fdiv_rn(x, 1.4142135623730951f);
    float e = xla_erf(u);
    return __fmul_rn(__fmul_rn(x, __fadd_rn(e, 1.0f)), 0.5f);
}

// ---------------- init ----------------
__global__ void k_init() {
    int t = blockIdx.x * blockDim.x + threadIdx.x;
    if (t < C_DIM) {
        g_xminC[t]  = INFINITY;
        g_xmaxC[t]  = -INFINITY;
        g_w1cmax[t] = 0.f;
    }
    if (t == 0) { g_habs = 0.f; g_omin = INFINITY; g_omax = -INFINITY; }
}

// ---------------- per-channel min/max of x ----------------
__global__ void k_xstats(const float* __restrict__ x) {
    int c  = blockIdx.x * 256 + threadIdx.x;
    int m0 = blockIdx.y * 197;
    float mn = INFINITY, mx = -INFINITY;
    const float* p = x + (size_t)m0 * C_DIM + c;
    #pragma unroll 4
    for (int i = 0; i < 197; ++i) {
        float v = p[(size_t)i * C_DIM];
        mn = fminf(mn, v); mx = fmaxf(mx, v);
    }
    atomicMinF(&g_xminC[c], mn);
    atomicMaxF(&g_xmaxC[c], mx);
}

// ---------------- per-channel absmax of w1 ----------------
__global__ void k_w1stats(const float* __restrict__ w1) {
    int c  = blockIdx.x * 256 + threadIdx.x;
    int h0 = blockIdx.y * 256;
    float mx = 0.f;
    const float* p = w1 + (size_t)h0 * C_DIM + c;
    #pragma unroll 4
    for (int i = 0; i < 256; ++i)
        mx = fmaxf(mx, fabsf(p[(size_t)i * C_DIM]));
    atomicMax((int*)&g_w1cmax[c], __float_as_int(mx));
}

// ---------------- cs + activation scale/zp ----------------
__global__ void k_scalars() {
    __shared__ float smn[256], smx[256];
    int tid = threadIdx.x;
    const float LN2F = 0.6931471805599453f;
    float mn = INFINITY, mx = -INFINITY;
    for (int c = tid; c < C_DIM; c += 256) {
        float xlo = g_xminC[c], xhi = g_xmaxC[c];
        float gmax = fmaxf(fabsf(xlo), fabsf(xhi));
        float mw = g_w1cmax[c];
        float csr = __fdiv_rn(sqrtf(gmax), sqrtf(mw));
        float y = floorf(__fdiv_rn(logf(csr), LN2F));
        float p = exp2f(y);
        float cs = (__fsub_rn(csr, p) > __fsub_rn(__fmul_rn(2.f, p), csr)) ? 2.f * p : p;
        g_cs[c] = cs;
        mn = fminf(mn, __fdiv_rn(xlo, cs));
        mx = fmaxf(mx, __fdiv_rn(xhi, cs));
    }
    smn[tid] = mn; smx[tid] = mx;
    __syncthreads();
    for (int s = 128; s > 0; s >>= 1) {
        if (tid < s) {
            smn[tid] = fminf(smn[tid], smn[tid + s]);
            smx[tid] = fmaxf(smx[tid], smx[tid + s]);
        }
        __syncthreads();
    }
    if (tid == 0) {
        float xmn = fminf(smn[0], 0.f);
        float xmx = fmaxf(smx[0], 0.f);
        float s = fmaxf(__fdiv_rn(__fsub_rn(xmx, xmn), 255.f), 1e-8f);
        float zp = rintf(__fdiv_rn(-xmn, s));
        g_sx = s; g_zp = zp; g_k128 = 128 - (int)zp;
    }
}

// ---------------- quantize x -> s8 (q - 128) ----------------
__global__ void k_quant_x(const float* __restrict__ x) {
    size_t i = (size_t)blockIdx.x * 256 + threadIdx.x;
    if (i >= (size_t)M_TOK * C_DIM) return;
    int c = (int)(i % C_DIM);
    float s = g_sx, zp = g_zp;
    float t = __fdiv_rn(x[i], g_cs[c]);
    float q = __fadd_rn(rintf(__fdiv_rn(t, s)), zp);
    q = fminf(fmaxf(q, 0.f), 255.f);
    g_qa[i] = (int8_t)((int)q - 128);
}

// ---------------- quantize w1 * cs (per output row) ----------------
__global__ void k_quant_w1(const float* __restrict__ w1) {
    __shared__ float red[256];
    int j = blockIdx.x, tid = threadIdx.x;
    const float* row = w1 + (size_t)j * C_DIM;
    float mx = 0.f;
    for (int c = tid; c < C_DIM; c += 256)
        mx = fmaxf(mx, fabsf(__fmul_rn(row[c], g_cs[c])));
    red[tid] = mx; __syncthreads();
    for (int s = 128; s > 0; s >>= 1) {
        if (tid < s) red[tid] = fmaxf(red[tid], red[tid + s]);
        __syncthreads();
    }
    float sc = fmaxf(__fdiv_rn(red[0], 127.f), 1e-8f);
    __syncthreads();
    for (int c = tid; c < C_DIM; c += 256) {
        float ws = __fmul_rn(row[c], g_cs[c]);
        float q = rintf(__fdiv_rn(ws, sc));
        q = fminf(fmaxf(q, -128.f), 127.f);
        g_qw1[(size_t)j * C_DIM + c] = (int8_t)(int)q;
    }
    if (tid == 0) g_sw1[j] = sc;
}

// ---------------- quantize w2 (per output row) ----------------
__global__ void k_quant_w2(const float* __restrict__ w2) {
    __shared__ float red[256];
    int j = blockIdx.x, tid = threadIdx.x;
    const float* row = w2 + (size_t)j * H_DIM;
    float mx = 0.f;
    for (int c = tid; c < H_DIM; c += 256)
        mx = fmaxf(mx, fabsf(row[c]));
    red[tid] = mx; __syncthreads();
    for (int s = 128; s > 0; s >>= 1) {
        if (tid < s) red[tid] = fmaxf(red[tid], red[tid + s]);
        __syncthreads();
    }
    float sc = fmaxf(__fdiv_rn(red[0], 127.f), 1e-8f);
    __syncthreads();
    for (int c = tid; c < H_DIM; c += 256) {
        float q = rintf(__fdiv_rn(row[c], sc));
        q = fminf(fmaxf(q, -128.f), 127.f);
        g_qw2[(size_t)j * H_DIM + c] = (int8_t)(int)q;
    }
    if (tid == 0) g_sw2[j] = sc;
}

// =====================================================================
// GEMM1: fp32 FMA chain per output, k ascending, one accumulator each.
// Packed two outputs per register via fma.rn.f32x2 (per-lane IEEE RN,
// bit-identical to scalar FFMA chains). Column pairing: acc2[i][j]
// holds cols (tx+16*(2j), tx+16*(2j+1)) of output row (ty+16*i).
// =====================================================================
__global__ __launch_bounds__(256, 2) void k_gemm1f(const float* __restrict__ b1) {
    __shared__ float As[128 * 17], Bs[128 * 17];
    __shared__ float red[256];
    unsigned long long acc2[8][4];
    const unsigned long long zz = pk2(0.f, 0.f);
    #pragma unroll
    for (int i = 0; i < 8; ++i)
        #pragma unroll
        for (int j = 0; j < 4; ++j) acc2[i][j] = zz;

    const int tid = threadIdx.x;
    const int ldRow = tid >> 1, ldSeg = tid & 1;  // 2 threads per row, 8 bytes each
    const int tx = tid & 15, ty = tid >> 4;
    const int aRow = blockIdx.y * 128 + ldRow;
    const int bRow = blockIdx.x * 128 + ldRow;
    const bool aValid = (aRow < M_TOK);
    const float sx = g_sx;
    const float k128f = (float)g_k128;
    const float swB = g_sw1[bRow];

    const int8_t* aP = g_qa + (size_t)aRow * C_DIM + ldSeg * 8;
    const int8_t* bP = g_qw1 + (size_t)bRow * C_DIM + ldSeg * 8;

    for (int kt = 0; kt < C_DIM; kt += 16) {
        uint2 avi = make_uint2(0u, 0u);
        if (aValid) avi = *reinterpret_cast<const uint2*>(aP + kt);
        uint2 bvi = *reinterpret_cast<const uint2*>(bP + kt);
        __syncthreads();
        {
            float* as = &As[ldRow * 17 + ldSeg * 8];
            float* bs = &Bs[ldRow * 17 + ldSeg * 8];
            #pragma unroll
            for (int t = 0; t < 4; ++t) {
                int a0 = (int)(int8_t)(avi.x >> (8 * t));
                int a1 = (int)(int8_t)(avi.y >> (8 * t));
                as[t]     = __fmul_rn((float)a0 + k128f, sx);
                as[t + 4] = __fmul_rn((float)a1 + k128f, sx);
                int b0 = (int)(int8_t)(bvi.x >> (8 * t));
                int b1v = (int)(int8_t)(bvi.y >> (8 * t));
                bs[t]     = __fmul_rn((float)b0, swB);
                bs[t + 4] = __fmul_rn((float)b1v, swB);
            }
        }
        __syncthreads();
        #pragma unroll
        for (int kk = 0; kk < 16; ++kk) {
            unsigned long long a2[8], b2[4];
            #pragma unroll
            for (int i = 0; i < 8; ++i) {
                float av = As[(ty + 16 * i) * 17 + kk];
                a2[i] = pk2(av, av);
            }
            #pragma unroll
            for (int j = 0; j < 4; ++j) {
                float blo = Bs[(tx + 16 * (2 * j)) * 17 + kk];
                float bhi = Bs[(tx + 16 * (2 * j + 1)) * 17 + kk];
                b2[j] = pk2(blo, bhi);
            }
            #pragma unroll
            for (int i = 0; i < 8; ++i)
                #pragma unroll
                for (int j = 0; j < 4; ++j)
                    acc2[i][j] = fma2(a2[i], b2[j], acc2[i][j]);
        }
    }

    // epilogue: h = chain + b1 (f32 add), exact GELU, max|h|
    float lmax = 0.f;
    #pragma unroll
    for (int j = 0; j < 4; ++j) {
        int colLo = blockIdx.x * 128 + tx + 16 * (2 * j);
        int colHi = colLo + 16;
        float bbLo = b1[colLo];
        float bbHi = b1[colHi];
        #pragma unroll
        for (int i = 0; i < 8; ++i) {
            int row = blockIdx.y * 128 + ty + 16 * i;
            if (row < M_TOK) {
                float aLo, aHi;
                upk2(acc2[i][j], aLo, aHi);
                float hvLo = __fadd_rn(aLo, bbLo);
                float hvHi = __fadd_rn(aHi, bbHi);
                float gLo = xla_gelu(hvLo);
                float gHi = xla_gelu(hvHi);
                g_h[(size_t)row * H_DIM + colLo] = gLo;
                g_h[(size_t)row * H_DIM + colHi] = gHi;
                lmax = fmaxf(lmax, fmaxf(fabsf(gLo), fabsf(gHi)));
            }
        }
    }
    red[tid] = lmax; __syncthreads();
    for (int s = 128; s > 0; s >>= 1) {
        if (tid < s) red[tid] = fmaxf(red[tid], red[tid + s]);
        __syncthreads();
    }
    if (tid == 0) atomicMax((int*)&g_habs, __float_as_int(red[0]));
}

// ---------------- symmetric quantize h -> s8 (vectorized x4) ----------------
__global__ void k_quant_h() {
    size_t i4 = (size_t)blockIdx.x * 256 + threadIdx.x;
    if (i4 >= (size_t)M_TOK * H_DIM / 4) return;
    float sh = fmaxf(__fdiv_rn(g_habs, 127.f), 1e-8f);
    const float4 v = reinterpret_cast<const float4*>(g_h)[i4];
    char4 o;
    float q;
    q = fminf(fmaxf(rintf(__fdiv_rn(v.x, sh)), -128.f), 127.f); o.x = (int8_t)(int)q;
    q = fminf(fmaxf(rintf(__fdiv_rn(v.y, sh)), -128.f), 127.f); o.y = (int8_t)(int)q;
    q = fminf(fmaxf(rintf(__fdiv_rn(v.z, sh)), -128.f), 127.f); o.z = (int8_t)(int)q;
    q = fminf(fmaxf(rintf(__fdiv_rn(v.w, sh)), -128.f), 127.f); o.w = (int8_t)(int)q;
    reinterpret_cast<char4*>(g_qh)[i4] = o;
}

// ---------------- GEMM2: dp4a integer (exact), fl32 once, + b2 in f32 ----------------
__global__ __launch_bounds__(256, 2) void k_gemm2(const float* __restrict__ b2,
                                                  float* __restrict__ out) {
    __shared__ uint32_t As[128 * 9], Bs[128 * 9];
    __shared__ float red[256];
    int acc[8][8];
    #pragma unroll
    for (int i = 0; i < 8; ++i)
        #pragma unroll
        for (int j = 0; j < 8; ++j) acc[i][j] = 0;

    const int tid = threadIdx.x;
    const int ldRow = tid >> 1, ldSeg = tid & 1;
    const int tx = tid & 15, ty = tid >> 4;
    const int aRow = blockIdx.y * 128 + ldRow;
    const int bRow = blockIdx.x * 128 + ldRow;
    const int8_t* aP = g_qh + (size_t)aRow * H_DIM + ldSeg * 16;
    const int8_t* bP = g_qw2 + (size_t)bRow * H_DIM + ldSeg * 16;
    const bool aValid = (aRow < M_TOK);

    for (int kt = 0; kt < H_DIM; kt += 32) {
        uint4 av = make_uint4(0u, 0u, 0u, 0u);
        if (aValid) av = *reinterpret_cast<const uint4*>(aP + kt);
        uint4 bv = *reinterpret_cast<const uint4*>(bP + kt);
        __syncthreads();
        uint32_t* as = &As[ldRow * 9 + ldSeg * 4];
        as[0] = av.x; as[1] = av.y; as[2] = av.z; as[3] = av.w;
        uint32_t* bs = &Bs[ldRow * 9 + ldSeg * 4];
        bs[0] = bv.x; bs[1] = bv.y; bs[2] = bv.z; bs[3] = bv.w;
        __syncthreads();
        #pragma unroll
        for (int kk = 0; kk < 8; ++kk) {
            uint32_t a[8], b[8];
            #pragma unroll
            for (int i = 0; i < 8; ++i) a[i] = As[(ty + 16 * i) * 9 + kk];
            #pragma unroll
            for (int jj = 0; jj < 8; ++jj) b[jj] = Bs[(tx + 16 * jj) * 9 + kk];
            #pragma unroll
            for (int i = 0; i < 8; ++i)
                #pragma unroll
                for (int jj = 0; jj < 8; ++jj)
                    acc[i][jj] = __dp4a((int)a[i], (int)b[jj], acc[i][jj]);
        }
    }

    const double sh = (double)fmaxf(__fdiv_rn(g_habs, 127.f), 1e-8f);
    float lmin = INFINITY, lmax = -INFINITY;
    #pragma unroll
    for (int j = 0; j < 8; ++j) {
        int col = blockIdx.x * 128 + tx + 16 * j;
        double coef = sh * (double)g_sw2[col];
        float bb = b2[col];
        #pragma unroll
        for (int i = 0; i < 8; ++i) {
            int row = blockIdx.y * 128 + ty + 16 * i;
            if (row < M_TOK) {
                float dot = (float)(coef * (double)acc[i][j]);  // fl32(exact dot)
                float v = __fadd_rn(dot, bb);                   // + b2 in f32
                out[(size_t)row * C_DIM + col] = v;
                lmin = fminf(lmin, v);
                lmax = fmaxf(lmax, v);
            }
        }
    }
    red[tid] = lmax; __syncthreads();
    for (int s = 128; s > 0; s >>= 1) {
        if (tid < s) red[tid] = fmaxf(red[tid], red[tid + s]);
        __syncthreads();
    }
    if (tid == 0) atomicMaxF(&g_omax, red[0]);
    __syncthreads();
    red[tid] = lmin; __syncthreads();
    for (int s = 128; s > 0; s >>= 1) {
        if (tid < s) red[tid] = fminf(red[tid], red[tid + s]);
        __syncthreads();
    }
    if (tid == 0) atomicMinF(&g_omin, red[0]);
}

// ---------------- final asymmetric fake-quant of out (in place) ----------------
__global__ void k_quant_out(float* __restrict__ out) {
    size_t i = (size_t)blockIdx.x * 256 + threadIdx.x;
    if (i >= (size_t)M_TOK * C_DIM) return;
    float omn = fminf(g_omin, 0.f);
    float omx = fmaxf(g_omax, 0.f);
    float s = fmaxf(__fdiv_rn(__fsub_rn(omx, omn), 255.f), 1e-8f);
    float zp = rintf(__fdiv_rn(-omn, s));
    float v = out[i];
    float q = fminf(fmaxf(__fadd_rn(rintf(__fdiv_rn(v, s)), zp), 0.f), 255.f);
    out[i] = __fmul_rn(__fsub_rn(q, zp), s);
}

// ---------------- launch ----------------
extern "C" void kernel_launch(void* const* d_in, const int* in_sizes, int n_in,
                              void* d_out, int out_size) {
    const float* x  = (const float*)d_in[0];
    const float* w1 = (const float*)d_in[1];
    const float* b1 = (const float*)d_in[2];
    const float* w2 = (const float*)d_in[3];
    const float* b2 = (const float*)d_in[4];
    float* out = (float*)d_out;

    k_init<<<3, 256>>>();
    k_xstats<<<dim3(3, 64), 256>>>(x);
    k_w1stats<<<dim3(3, 12), 256>>>(w1);
    k_scalars<<<1, 256>>>();

    size_t nx = (size_t)M_TOK * C_DIM;
    k_quant_x<<<(unsigned)((nx + 255) / 256), 256>>>(x);
    k_quant_w1<<<H_DIM, 256>>>(w1);
    k_quant_w2<<<C_DIM, 256>>>(w2);

    k_gemm1f<<<dim3(H_DIM / 128, (M_TOK + 127) / 128), 256>>>(b1);

    size_t nh4 = (size_t)M_TOK * H_DIM / 4;
    k_quant_h<<<(unsigned)((nh4 + 255) / 256), 256>>>();

    k_gemm2<<<dim3(C_DIM / 128, (M_TOK + 127) / 128), 256>>>(b2, out);

    k_quant_out<<<(unsigned)((nx + 255) / 256), 256>>>(out);
}